// round 16
// baseline (speedup 1.0000x reference)
#include <cuda_runtime.h>
#include <math.h>

#define BB 2
#define NN 512
#define DIMV 256
#define HH 8
#define DHV 32
#define SCALEV 0.17677669529663687f   // 32^-0.5
#define SLP 516                        // sL pitch (floats)

// ---------------- scratch (device globals; no allocation) ----------------
__device__ float g_q [BB*HH*NN*DHV];     // [b][h][i][d]
__device__ float g_k [BB*HH*NN*DHV];     // [b][h][j][d]
__device__ float g_v [BB*HH*NN*DHV];     // [b][h][j][d]
__device__ float g_qW[BB*NN*HH*256];     // [(b,i)][h][c]
__device__ float g_qk[BB*NN*HH*NN];      // [(b,i)][h][j]
__device__ float g_at[BB*NN*HH*NN];      // attn, same layout
__device__ float g_ae[BB*NN*HH*256];     // [(b,i)][h][c]
__device__ float g_ov[BB*NN*DIMV];       // [(b,i)][h*32+d]
__device__ float g_u [BB*NN*DIMV];       // [(b,i)][h*32+d]

// ---------------- packed f32x2 helpers ----------------
__device__ __forceinline__ void ffma2(unsigned long long& d,
                                      unsigned long long a, unsigned long long b) {
    asm("fma.rn.f32x2 %0, %1, %2, %0;" : "+l"(d) : "l"(a), "l"(b));
}
__device__ __forceinline__ void mul2(unsigned long long& d, unsigned long long a) {
    asm("mul.rn.f32x2 %0, %0, %1;" : "+l"(d) : "l"(a));
}
__device__ __forceinline__ unsigned long long pack2(float x) {
    unsigned long long r;
    asm("mov.b64 %0, {%1, %1};" : "=l"(r) : "f"(x));
    return r;
}
__device__ __forceinline__ void unpack2(unsigned long long v, float& lo, float& hi) {
    asm("mov.b64 {%0, %1}, %2;" : "=f"(lo), "=f"(hi) : "l"(v));
}

// ================= K1: projections q,k,v (transposed per-head) =================
__global__ void k_proj(const float* __restrict__ nodes,
                       const float* __restrict__ Wq,  const float* __restrict__ bq,
                       const float* __restrict__ Wkv, const float* __restrict__ bkv) {
    extern __shared__ float sm[];
    float* sN = sm;            // [32][256]
    float* sW = sm + 32*256;   // [256][33]
    int cb = blockIdx.x, rb = blockIdx.y;
    int tid = threadIdx.x;
    int rowbase = rb*32;
    #pragma unroll 8
    for (int k = 0; k < 32; k++)
        sN[k*256 + tid] = nodes[(size_t)(rowbase + k)*256 + tid];
    int d = tid & 31, cw = tid >> 5;
    int col = cb*32 + d;
    const float* Wsrc; int ldw; int wcol;
    if (col < 256) { Wsrc = Wq;  ldw = 256; wcol = col; }
    else           { Wsrc = Wkv; ldw = 512; wcol = col - 256; }
    #pragma unroll 8
    for (int k = 0; k < 32; k++) {
        int c = k*8 + cw;
        sW[c*33 + d] = Wsrc[(size_t)c*ldw + wcol];
    }
    __syncthreads();
    int w = tid >> 5;
    float a0=0,a1=0,a2=0,a3=0;
    #pragma unroll 4
    for (int c = 0; c < 256; c++) {
        float wv = sW[c*33 + d];
        a0 += sN[ w      *256 + c]*wv;
        a1 += sN[(w + 8 )*256 + c]*wv;
        a2 += sN[(w + 16)*256 + c]*wv;
        a3 += sN[(w + 24)*256 + c]*wv;
    }
    float acc[4] = {a0,a1,a2,a3};
    float bias = (col < 256) ? bq[col] : bkv[col - 256];
    int sec = cb >> 3, hh = cb & 7;
    float* dst = (sec == 0) ? g_q : (sec == 1) ? g_k : g_v;
    #pragma unroll
    for (int k = 0; k < 4; k++) {
        int row = rowbase + w + k*8;
        int b = row >> 9, i = row & 511;
        dst[(((size_t)(b*8 + hh))*512 + i)*32 + d] = acc[k] + bias;
    }
}

// ================= K2: qW[b,i,h,c] = sum_d q[b,h,i,d]*We[c,h*32+d] =================
__global__ void k_qw(const float* __restrict__ We) {
    __shared__ float sW[32*257];
    __shared__ float sq[32*32];
    int rb = blockIdx.x, h = blockIdx.y;
    int tid = threadIdx.x;
    int d = tid & 31, cw = tid >> 5;
    #pragma unroll 8
    for (int k = 0; k < 32; k++) {
        int c = k*8 + cw;
        sW[d*257 + c] = We[(size_t)c*256 + h*32 + d];
    }
    #pragma unroll
    for (int k = 0; k < 4; k++) {
        int idx = k*256 + tid; int r = idx >> 5; int dd = idx & 31;
        int row = rb*32 + r; int b = row >> 9, i = row & 511;
        sq[r*32 + dd] = g_q[(((size_t)(b*8 + h))*512 + i)*32 + dd];
    }
    __syncthreads();
    int c = tid;
    for (int r = 0; r < 32; r++) {
        float acc = 0.f;
        #pragma unroll
        for (int dd = 0; dd < 32; dd++) acc += sq[r*32 + dd] * sW[dd*257 + c];
        int row = rb*32 + r;
        g_qW[(((size_t)row)*8 + h)*256 + c] = acc;
    }
}

// ================= K3: qk[b,i,h,j] = q_h[i]·k_h[j] =================
__global__ void k_qk() {
    __shared__ float Qs[64*33], Ks[64*33];
    int jt = blockIdx.x, it = blockIdx.y, bh = blockIdx.z;
    int tid = threadIdx.x;
    #pragma unroll
    for (int k = 0; k < 8; k++) {
        int idx = k*256 + tid; int r = idx >> 5, d = idx & 31;
        Qs[r*33 + d] = g_q[(((size_t)bh)*512 + it*64 + r)*32 + d];
        Ks[r*33 + d] = g_k[(((size_t)bh)*512 + jt*64 + r)*32 + d];
    }
    __syncthreads();
    int tx = tid & 15, ty = tid >> 4;
    float acc[4][4] = {};
    #pragma unroll 8
    for (int dd = 0; dd < 32; dd++) {
        float qr[4], kr[4];
        #pragma unroll
        for (int a = 0; a < 4; a++) qr[a] = Qs[(ty*4 + a)*33 + dd];
        #pragma unroll
        for (int a = 0; a < 4; a++) kr[a] = Ks[(tx*4 + a)*33 + dd];
        #pragma unroll
        for (int a = 0; a < 4; a++)
            #pragma unroll
            for (int b2 = 0; b2 < 4; b2++) acc[a][b2] += qr[a]*kr[b2];
    }
    int b = bh >> 3, h = bh & 7;
    #pragma unroll
    for (int a = 0; a < 4; a++) {
        int i = it*64 + ty*4 + a;
        size_t base = (((size_t)(b*512 + i))*8 + h)*512 + jt*64 + tx*4;
        #pragma unroll
        for (int b2 = 0; b2 < 4; b2++) g_qk[base + b2] = acc[a][b2];
    }
}

// ================= K4 v3: online-softmax single-stream edge kernel =================
// grid 1024 (one per (b,i)), 256 thr, 2 blocks/SM, static smem 43.5KB
// per j-tile(64): sub1 logits (E from DRAM) -> smax update -> sub2 ae accum (E L1-hot)
__global__ __launch_bounds__(256, 2) void k_passAB(const float* __restrict__ edges) {
    __shared__ float sL[8*SLP];        // raw logits (qk preloaded, then += qe, *SCALE)
    __shared__ float sQ[16*130];       // qW, bank-swizzled: [csplit][h][q][2]
    __shared__ float sP[8*68];         // per-tile unnormalized p
    __shared__ float sRed[2*8*256];    // jsp partials for ae
    __shared__ float sM[8], sLsum[8], sF[8], sInv[8];

    int bi = blockIdx.x, tid = threadIdx.x;
    const float* Eb  = edges + (size_t)bi*512*256;
    const float* qWb = g_qW  + (size_t)bi*8*256;

    // preload qk logit bases
    #pragma unroll
    for (int k = 0; k < 16; k++) {
        int idx = k*256 + tid; int h = idx >> 9, j = idx & 511;
        sL[h*SLP + j] = g_qk[((size_t)bi*8 + h)*512 + j];
    }
    // stage qW into swizzled smem (conflict-free LDS.64 reads in sub1)
    #pragma unroll
    for (int k = 0; k < 8; k++) {
        int idx = k*256 + tid; int h = idx >> 8, c = idx & 255;
        int cs = c >> 4, q = (c & 15) >> 1, e = c & 1;
        sQ[cs*130 + h*16 + q*2 + e] = qWb[(size_t)h*256 + c];
    }
    if (tid < 8) { sM[tid] = -1e30f; sLsum[tid] = 0.f; }

    const int csplit = tid & 15, hs = (tid >> 4) & 1, wl = tid >> 5;
    const int lane = tid & 31;
    const int cch = tid & 127, jsp = tid >> 7;

    unsigned long long acc[8];
    #pragma unroll
    for (int h = 0; h < 8; h++) acc[h] = 0ull;

    __syncthreads();

    for (int t = 0; t < 8; t++) {
        // ---------- sub1: logits for rows [t*64, t*64+64) ----------
        {
            unsigned long long qw[4][8];
            #pragma unroll
            for (int a = 0; a < 4; a++)
                #pragma unroll
                for (int q = 0; q < 8; q++)
                    qw[a][q] = *(const unsigned long long*)
                               &sQ[csplit*130 + (hs*4 + a)*16 + q*2];
            const char* rowp = (const char*)(Eb + (size_t)(t*64 + wl*8)*256 + csplit*16);
            ulonglong2 e[4];
            #pragma unroll
            for (int q = 0; q < 4; q++) e[q] = ((const ulonglong2*)rowp)[q];
            #pragma unroll
            for (int k = 0; k < 8; k++) {
                const char* nxt = rowp + 1024;
                ulonglong2 en[4];
                #pragma unroll
                for (int q = 0; q < 4; q++) en[q] = e[q];
                if (k < 7) {
                    #pragma unroll
                    for (int q = 0; q < 4; q++) en[q] = ((const ulonglong2*)nxt)[q];
                }
                float s[4];
                #pragma unroll
                for (int a = 0; a < 4; a++) {
                    unsigned long long ac = 0ull;
                    #pragma unroll
                    for (int q = 0; q < 4; q++) {
                        ffma2(ac, e[q].x, qw[a][2*q]);
                        ffma2(ac, e[q].y, qw[a][2*q + 1]);
                    }
                    float lo, hi; unpack2(ac, lo, hi);
                    s[a] = lo + hi;
                }
                #pragma unroll
                for (int a = 0; a < 4; a++) {
                    s[a] += __shfl_xor_sync(0xffffffffu, s[a], 1);
                    s[a] += __shfl_xor_sync(0xffffffffu, s[a], 2);
                    s[a] += __shfl_xor_sync(0xffffffffu, s[a], 4);
                    s[a] += __shfl_xor_sync(0xffffffffu, s[a], 8);
                }
                int j = t*64 + wl*8 + k;
                if (csplit < 4) {
                    int h = hs*4 + csplit;
                    sL[h*SLP + j] = (sL[h*SLP + j] + s[csplit]) * SCALEV;
                }
                #pragma unroll
                for (int q = 0; q < 4; q++) e[q] = en[q];
                rowp = nxt;
            }
        }
        __syncthreads();

        // ---------- online softmax update: warp wl == head wl ----------
        {
            const float* row = sL + wl*SLP + t*64;
            float v0 = row[lane], v1 = row[lane + 32];
            float m = fmaxf(v0, v1);
            #pragma unroll
            for (int o = 16; o > 0; o >>= 1)
                m = fmaxf(m, __shfl_xor_sync(0xffffffffu, m, o));
            float mold = sM[wl];
            float mnew = fmaxf(mold, m);
            float f  = __expf(mold - mnew);
            float p0 = __expf(v0 - mnew);
            float p1 = __expf(v1 - mnew);
            sP[wl*68 + lane]      = p0;
            sP[wl*68 + lane + 32] = p1;
            float ssum = p0 + p1;
            #pragma unroll
            for (int o = 16; o > 0; o >>= 1)
                ssum += __shfl_xor_sync(0xffffffffu, ssum, o);
            if (lane == 0) {
                sM[wl] = mnew;
                sLsum[wl] = sLsum[wl]*f + ssum;
                sF[wl] = f;
            }
        }
        __syncthreads();

        // ---------- sub2: ae accumulate over this tile (E re-read, L1-hot) ----------
        {
            #pragma unroll
            for (int h = 0; h < 8; h++) mul2(acc[h], pack2(sF[h]));
            const char* rp = (const char*)(Eb + (size_t)(t*64 + jsp*32)*256 + cch*2);
            #pragma unroll
            for (int r4 = 0; r4 < 8; r4++) {
                float4 pv[8];
                #pragma unroll
                for (int h = 0; h < 8; h++)
                    pv[h] = *(const float4*)&sP[h*68 + jsp*32 + r4*4];
                unsigned long long ev[4];
                #pragma unroll
                for (int r = 0; r < 4; r++)
                    ev[r] = *(const unsigned long long*)(rp + (size_t)(r4*4 + r)*1024);
                #pragma unroll
                for (int r = 0; r < 4; r++) {
                    #pragma unroll
                    for (int h = 0; h < 8; h++) {
                        float av = (r == 0) ? pv[h].x : (r == 1) ? pv[h].y
                                 : (r == 2) ? pv[h].z : pv[h].w;
                        ffma2(acc[h], pack2(av), ev[r]);
                    }
                }
            }
        }
        // no sync needed: next sub1 writes a disjoint sL region; sP/sF rewritten
        // only after the sync that follows next sub1.
    }

    // stage jsp partials
    #pragma unroll
    for (int h = 0; h < 8; h++)
        *(unsigned long long*)&sRed[(jsp*8 + h)*256 + cch*2] = acc[h];
    if (tid < 8) sInv[tid] = 1.0f / sLsum[tid];
    __syncthreads();

    // final: normalized ae
    #pragma unroll
    for (int k = 0; k < 8; k++) {
        int idx = k*256 + tid; int h = idx >> 8, c = idx & 255;
        float v = (sRed[h*256 + c] + sRed[(8 + h)*256 + c]) * sInv[h];
        g_ae[((size_t)bi*8 + h)*256 + c] = v;
    }
    // final: normalized attn from raw logits
    #pragma unroll
    for (int k = 0; k < 16; k++) {
        int idx = k*256 + tid; int h = idx >> 9, j = idx & 511;
        g_at[((size_t)bi*8 + h)*512 + j] =
            __expf(sL[h*SLP + j] - sM[h]) * sInv[h];
    }
}

// ================= K5: ov = attn @ v =================
__global__ void k_outv() {
    __shared__ float sA[64*65];
    __shared__ float sV[64*33];
    int it = blockIdx.x, h = blockIdx.y, b = blockIdx.z;
    int tid = threadIdx.x;
    int ii = tid >> 2, dg = tid & 3, d0 = dg*8;
    float acc[8] = {};
    for (int jc = 0; jc < 8; jc++) {
        #pragma unroll
        for (int k = 0; k < 16; k++) {
            int idx = k*256 + tid; int r = idx >> 6, c = idx & 63;
            sA[r*65 + c] = g_at[(((size_t)(b*512 + it*64 + r))*8 + h)*512 + jc*64 + c];
        }
        #pragma unroll
        for (int k = 0; k < 8; k++) {
            int idx = k*256 + tid; int r = idx >> 5, c = idx & 31;
            sV[r*33 + c] = g_v[(((size_t)(b*8 + h))*512 + jc*64 + r)*32 + c];
        }
        __syncthreads();
        #pragma unroll 4
        for (int jl = 0; jl < 64; jl++) {
            float a = sA[ii*65 + jl];
            #pragma unroll
            for (int dd = 0; dd < 8; dd++) acc[dd] += a * sV[jl*33 + d0 + dd];
        }
        __syncthreads();
    }
    size_t obase = ((size_t)(b*512 + it*64 + ii))*256 + h*32 + d0;
    #pragma unroll
    for (int dd = 0; dd < 8; dd++) g_ov[obase + dd] = acc[dd];
}

// ================= K6: u = ov + ae@We_h + be =================
__global__ void k_oe(const float* __restrict__ We, const float* __restrict__ be) {
    extern __shared__ float sm[];
    float* sW = sm;            // [256][33]
    float* sa = sm + 256*33;   // [32][257]
    int rb = blockIdx.x, h = blockIdx.y;
    int tid = threadIdx.x;
    int d = tid & 31, cw = tid >> 5;
    #pragma unroll 8
    for (int k = 0; k < 32; k++) {
        int c = k*8 + cw;
        sW[c*33 + d] = We[(size_t)c*256 + h*32 + d];
    }
    #pragma unroll 8
    for (int k = 0; k < 32; k++)
        sa[k*257 + tid] = g_ae[(((size_t)(rb*32 + k))*8 + h)*256 + tid];
    __syncthreads();
    int w = tid >> 5;
    float a0=0,a1=0,a2=0,a3=0;
    #pragma unroll 4
    for (int c = 0; c < 256; c++) {
        float wv = sW[c*33 + d];
        a0 += sa[ w      *257 + c]*wv;
        a1 += sa[(w + 8 )*257 + c]*wv;
        a2 += sa[(w + 16)*257 + c]*wv;
        a3 += sa[(w + 24)*257 + c]*wv;
    }
    float acc[4] = {a0,a1,a2,a3};
    float bias = be[h*32 + d];
    #pragma unroll
    for (int k = 0; k < 4; k++) {
        size_t o = ((size_t)(rb*32 + w + k*8))*256 + h*32 + d;
        g_u[o] = acc[k] + bias + g_ov[o];
    }
}

// ================= K7: out = u @ Wo + bo =================
__global__ void k_final(const float* __restrict__ Wo, const float* __restrict__ bo,
                        float* __restrict__ out) {
    extern __shared__ float sm[];
    float* sW = sm;            // [256][33]
    float* su = sm + 256*33;   // [32][257]
    int cb = blockIdx.x, rb = blockIdx.y;
    int tid = threadIdx.x;
    int d = tid & 31, cw = tid >> 5;
    #pragma unroll 8
    for (int k = 0; k < 32; k++) {
        int c = k*8 + cw;
        sW[c*33 + d] = Wo[(size_t)c*256 + cb*32 + d];
    }
    #pragma unroll 8
    for (int k = 0; k < 32; k++)
        su[k*257 + tid] = g_u[((size_t)(rb*32 + k))*256 + tid];
    __syncthreads();
    int w = tid >> 5;
    float a0=0,a1=0,a2=0,a3=0;
    #pragma unroll 4
    for (int c = 0; c < 256; c++) {
        float wv = sW[c*33 + d];
        a0 += su[ w      *257 + c]*wv;
        a1 += su[(w + 8 )*257 + c]*wv;
        a2 += su[(w + 16)*257 + c]*wv;
        a3 += su[(w + 24)*257 + c]*wv;
    }
    float acc[4] = {a0,a1,a2,a3};
    float bias = bo[cb*32 + d];
    #pragma unroll
    for (int k = 0; k < 4; k++)
        out[((size_t)(rb*32 + w + k*8))*256 + cb*32 + d] = acc[k] + bias;
}

// ================= launch =================
extern "C" void kernel_launch(void* const* d_in, const int* in_sizes, int n_in,
                              void* d_out, int out_size) {
    const float* nodes = (const float*)d_in[0];
    const float* edges = (const float*)d_in[1];
    const float* Wq    = (const float*)d_in[2];
    const float* bq    = (const float*)d_in[3];
    const float* Wkv   = (const float*)d_in[4];
    const float* bkv   = (const float*)d_in[5];
    const float* We    = (const float*)d_in[6];
    const float* be    = (const float*)d_in[7];
    const float* Wo    = (const float*)d_in[8];
    const float* bo    = (const float*)d_in[9];
    float* out = (float*)d_out;

    cudaFuncSetAttribute(k_proj,  cudaFuncAttributeMaxDynamicSharedMemorySize, 66560);
    cudaFuncSetAttribute(k_oe,    cudaFuncAttributeMaxDynamicSharedMemorySize, 66688);
    cudaFuncSetAttribute(k_final, cudaFuncAttributeMaxDynamicSharedMemorySize, 66688);

    k_proj  <<<dim3(24, 32),    256, 66560>>>(nodes, Wq, bq, Wkv, bkv);
    k_qw    <<<dim3(32, 8),     256>>>(We);
    k_qk    <<<dim3(8, 8, 16),  256>>>();
    k_passAB<<<1024,            256>>>(edges);
    k_outv  <<<dim3(8, 8, 2),   256>>>();
    k_oe    <<<dim3(32, 8),     256, 66688>>>(We, be);
    k_final <<<dim3(8, 32),     256, 66688>>>(Wo, bo, out);
}